// round 15
// baseline (speedup 1.0000x reference)
#include <cuda_runtime.h>

// out[i, :] = values[i] * W_D[layer_idx[i], feat_idx[i], :]
// W_D: (12, 16384, 768) fp32; nnz = 131072; d_model = 768 (3072 B/row).
//
// R9: DRAM direction-batching. 4 chunks of 32768 rows. Per chunk:
//   1) prefetch kernel: ldcg all gathered W rows -> chunk's distinct rows
//      (~73MB) become L2-resident. DRAM phase = (almost) pure reads.
//   2) scale+write kernel: ldcg reads hit L2; __stwt writes stream to DRAM
//      without allocating in L2 (prefetched rows stay). DRAM phase = pure
//      writes. Bus turnaround happens per chunk, not per transaction.

#define D_SAE   16384
#define D_MODEL 768
#define VEC_PER_ROW (D_MODEL / 4)   // 192
#define ROWS_PER_CTA 8
#define N_CHUNKS 4

__global__ __launch_bounds__(VEC_PER_ROW)
void prefetch_kernel(const float4* __restrict__ W,
                     const int*    __restrict__ li,
                     const int*    __restrict__ fi,
                     int row_base)
{
    const int row0 = row_base + blockIdx.x * ROWS_PER_CTA;
    const int c    = threadIdx.x;

#pragma unroll
    for (int r = 0; r < ROWS_PER_CTA; r++) {
        const int row   = row0 + r;
        const int layer = __ldg(&li[row]);
        const int feat  = __ldg(&fi[row]);
        float4 d = __ldcg(&W[(unsigned int)(layer * D_SAE + feat) * VEC_PER_ROW + c]);
        // consume so the load isn't dead-code eliminated; no stores
        asm volatile("" :: "f"(d.x), "f"(d.y), "f"(d.z), "f"(d.w));
    }
}

__global__ __launch_bounds__(VEC_PER_ROW, 6)
void scale_write_kernel(const float4* __restrict__ W,
                        const float*  __restrict__ vals,
                        const int*    __restrict__ li,
                        const int*    __restrict__ fi,
                        float4*       __restrict__ out,
                        int row_base)
{
    const int row0 = row_base + blockIdx.x * ROWS_PER_CTA;
    const int c    = threadIdx.x;

    unsigned int src[ROWS_PER_CTA];
    float        v[ROWS_PER_CTA];

#pragma unroll
    for (int r = 0; r < ROWS_PER_CTA; r++) {
        const int row   = row0 + r;
        const int layer = __ldg(&li[row]);
        const int feat  = __ldg(&fi[row]);
        v[r]            = __ldg(&vals[row]);
        src[r] = (unsigned int)(layer * D_SAE + feat) * VEC_PER_ROW + c;
    }

    float4 d[ROWS_PER_CTA];
#pragma unroll
    for (int r = 0; r < ROWS_PER_CTA; r++)
        d[r] = __ldcg(&W[src[r]]);          // L2 hit (prefetched)

#pragma unroll
    for (int r = 0; r < ROWS_PER_CTA; r++) {
        float4 o = d[r];
        o.x *= v[r]; o.y *= v[r]; o.z *= v[r]; o.w *= v[r];
        // write-through: don't evict the prefetched W rows from L2
        __stwt(&out[(unsigned int)(row0 + r) * VEC_PER_ROW + c], o);
    }
}

extern "C" void kernel_launch(void* const* d_in, const int* in_sizes, int n_in,
                              void* d_out, int out_size)
{
    const float4* W    = (const float4*)d_in[0];
    const float*  vals = (const float*) d_in[1];
    const int*    li   = (const int*)   d_in[2];
    // d_in[3] = pos_idx (unused)
    const int*    fi   = (const int*)   d_in[4];
    float4*       out  = (float4*)      d_out;

    const int nnz        = in_sizes[1];               // 131072
    const int chunk_rows = nnz / N_CHUNKS;            // 32768
    const int chunk_grid = chunk_rows / ROWS_PER_CTA; // 4096

    for (int ck = 0; ck < N_CHUNKS; ck++) {
        const int base = ck * chunk_rows;
        prefetch_kernel<<<chunk_grid, VEC_PER_ROW>>>(W, li, fi, base);
        scale_write_kernel<<<chunk_grid, VEC_PER_ROW>>>(W, vals, li, fi, out, base);
    }
}